// round 6
// baseline (speedup 1.0000x reference)
#include <cuda_runtime.h>
#include <cuda_bf16.h>

// -------------------------------------------------------------------------
// out = Conv2(ReLU(Conv1( sum_t Ht[t,:,:] * upsample4(yt[b,t]) )))
//   yt: (32,32,64,64) f32, Ht: (32,256,256) f32
//   W1: (32,1,3,3), b1:(32), W2:(1,32,3,3), b2:(1)
//   out: (32,1,256,256) f32
// -------------------------------------------------------------------------

#define B_     32
#define T_     32
#define R_     256

// stage-1 scratch x[b,p,q]  (8.4 MB, static device array — no allocs)
__device__ float g_x[B_ * R_ * R_];

// ---------------- Stage 1: x[b,p,q] = sum_t Ht[t,p,q] * yt[b,t,p/4,q/4] ----
__global__ void __launch_bounds__(256) stage1_kernel(
    const float* __restrict__ yt, const float* __restrict__ Ht)
{
    int idx = blockIdx.x * 256 + threadIdx.x;   // pixel linear index
    int p = idx >> 8;
    int q = idx & 255;
    int yoff = ((p >> 2) << 6) + (q >> 2);      // (p/4)*64 + q/4

    float ht[T_];
#pragma unroll
    for (int t = 0; t < T_; t++)
        ht[t] = Ht[(t << 16) + idx];            // coalesced across q

    int bbase = blockIdx.y << 3;                // 8 batches per block
#pragma unroll 2
    for (int bo = 0; bo < 8; bo++) {
        int b = bbase + bo;
        const float* ytb = yt + ((long)b << 17) + yoff;
        float acc = 0.f;
#pragma unroll
        for (int t = 0; t < T_; t++)
            acc = fmaf(ht[t], ytb[t << 12], acc);
        g_x[((long)b << 16) + idx] = acc;
    }
}

// ---------------- Stage 2: fused Conv1(1->32)+ReLU+Conv2(32->1), 3x3 SAME ----
// One block per (batch, 32x32 tile). Channels processed in 4 groups of 8 so
// everything fits in <48 KB static SMEM.
//
//   sx : [36][40]     x tile rows P0-2..P0+33 (36 cols used), zero-padded
//   sh : [8][34][36]  current group's conv1+ReLU output (h1 rows P0-1..P0+32,
//                     cols Q0-1..Q0+34); entries outside the image are ZEROED
//                     to match conv2's SAME zero-padding of h1.
//   sw2: [32*9]       conv2 weights
#define GROUPS     4
#define GC         8            // channels per group
#define SH_ELEMS   (GC * 34 * 36)
#define SX_ELEMS   (36 * 40)

__global__ void __launch_bounds__(256) fused_conv_kernel(
    const float* __restrict__ W1, const float* __restrict__ b1,
    const float* __restrict__ W2, const float* __restrict__ b2,
    float* __restrict__ out)
{
    __shared__ float sh[SH_ELEMS];    // 39168 B
    __shared__ float sx[SX_ELEMS];    //  5760 B
    __shared__ float sw2[32 * 9];     //  1152 B   -> 46080 B total

    int tid = threadIdx.x;
    int b   = blockIdx.y;
    int P0  = (blockIdx.x >> 3) << 5;
    int Q0  = (blockIdx.x & 7)  << 5;
    const float* xb = g_x + ((long)b << 16);

    // ---- load x tile (36x36 valid, row stride 40), zero halo ----
    for (int i = tid; i < SX_ELEMS; i += 256) {
        int r  = i / 40;
        int cc = i - r * 40;
        int gp = P0 - 2 + r;
        int gq = Q0 - 2 + cc;
        float v = 0.f;
        if (cc < 36 && (unsigned)gp < 256u && (unsigned)gq < 256u)
            v = xb[(gp << 8) + gq];
        sx[i] = v;
    }
    for (int i = tid; i < 32 * 9; i += 256) sw2[i] = W2[i];   // 288 > 256: stride
    __syncthreads();

    // persistent conv2 accumulators: each thread owns a 1x4 output strip
    int ty = tid >> 3;            // 0..31 output row in tile
    int tx = (tid & 7) << 2;      // 0,4,...,28 output col base
    float bb = *b2;
    float acc0 = bb, acc1 = bb, acc2 = bb, acc3 = bb;

    for (int g = 0; g < GROUPS; g++) {
        // ---- Conv1 + ReLU for this channel group into sh ----
        // thread -> channel c8 = tid/32 (8 channels), unit u = tid%32;
        // 34 rows x 9 four-wide segments = 306 units per channel, stride 32.
        {
            int c8 = tid >> 5;
            int u  = tid & 31;
            int c  = g * GC + c8;
            float w[9];
#pragma unroll
            for (int k = 0; k < 9; k++) w[k] = W1[c * 9 + k];
            float bias = b1[c];
            float* shc = sh + c8 * (34 * 36);

            for (int unit = u; unit < 306; unit += 32) {
                int r   = unit / 9;
                int s   = unit - r * 9;
                int col = s << 2;                    // 0..32
                const float* x0 = sx + r * 40 + col;
                float a0 = bias, a1 = bias, a2 = bias, a3 = bias;
#pragma unroll
                for (int dy = 0; dy < 3; dy++) {
                    const float* xr = x0 + dy * 40;
                    float4 v4 = *(const float4*)xr;
                    float2 v2 = *(const float2*)(xr + 4);
                    float v0 = v4.x, v1 = v4.y, vv2 = v4.z, v3 = v4.w;
                    float v4s = v2.x, v5 = v2.y;
                    float w0 = w[dy * 3], w1 = w[dy * 3 + 1], w2 = w[dy * 3 + 2];
                    a0 = fmaf(w0, v0,  a0); a0 = fmaf(w1, v1,  a0); a0 = fmaf(w2, vv2, a0);
                    a1 = fmaf(w0, v1,  a1); a1 = fmaf(w1, vv2, a1); a1 = fmaf(w2, v3,  a1);
                    a2 = fmaf(w0, vv2, a2); a2 = fmaf(w1, v3,  a2); a2 = fmaf(w2, v4s, a2);
                    a3 = fmaf(w0, v3,  a3); a3 = fmaf(w1, v4s, a3); a3 = fmaf(w2, v5,  a3);
                }
                a0 = fmaxf(a0, 0.f); a1 = fmaxf(a1, 0.f);
                a2 = fmaxf(a2, 0.f); a3 = fmaxf(a3, 0.f);
                // FIX: conv2's SAME padding sees h1 == 0 outside the image.
                // Zero any h1 value whose global position is out of bounds.
                {
                    bool rok = (unsigned)(P0 - 1 + r) < 256u;
                    int  gq  = Q0 - 1 + col;
                    a0 = (rok && (unsigned)(gq + 0) < 256u) ? a0 : 0.f;
                    a1 = (rok && (unsigned)(gq + 1) < 256u) ? a1 : 0.f;
                    a2 = (rok && (unsigned)(gq + 2) < 256u) ? a2 : 0.f;
                    a3 = (rok && (unsigned)(gq + 3) < 256u) ? a3 : 0.f;
                }
                *(float4*)(shc + r * 36 + col) = make_float4(a0, a1, a2, a3);
            }
        }
        __syncthreads();

        // ---- Conv2 partial accumulation over this group's 8 channels ----
#pragma unroll
        for (int c8 = 0; c8 < GC; c8++) {
            const float* hc = sh + c8 * (34 * 36);
            const float* wp = sw2 + (g * GC + c8) * 9;
            float w[9];
#pragma unroll
            for (int k = 0; k < 9; k++) w[k] = wp[k];
#pragma unroll
            for (int dy = 0; dy < 3; dy++) {
                const float* row = hc + (ty + dy) * 36 + tx;
                float4 v4 = *(const float4*)row;
                float2 v2 = *(const float2*)(row + 4);
                float v0 = v4.x, v1 = v4.y, vv2 = v4.z, v3 = v4.w;
                float v4s = v2.x, v5 = v2.y;
                float w0 = w[dy * 3], w1 = w[dy * 3 + 1], w2 = w[dy * 3 + 2];
                acc0 = fmaf(w0, v0,  acc0); acc0 = fmaf(w1, v1,  acc0); acc0 = fmaf(w2, vv2, acc0);
                acc1 = fmaf(w0, v1,  acc1); acc1 = fmaf(w1, vv2, acc1); acc1 = fmaf(w2, v3,  acc1);
                acc2 = fmaf(w0, vv2, acc2); acc2 = fmaf(w1, v3,  acc2); acc2 = fmaf(w2, v4s, acc2);
                acc3 = fmaf(w0, v3,  acc3); acc3 = fmaf(w1, v4s, acc3); acc3 = fmaf(w2, v5,  acc3);
            }
        }
        __syncthreads();   // before next group overwrites sh
    }

    float* ob = out + ((long)b << 16) + ((P0 + ty) << 8) + Q0 + tx;
    *(float4*)ob = make_float4(acc0, acc1, acc2, acc3);
}

// -------------------------------------------------------------------------
extern "C" void kernel_launch(void* const* d_in, const int* in_sizes, int n_in,
                              void* d_out, int out_size)
{
    const float* yt = (const float*)d_in[0];
    const float* Ht = (const float*)d_in[1];
    const float* W1 = (const float*)d_in[2];
    const float* b1 = (const float*)d_in[3];
    const float* W2 = (const float*)d_in[4];
    const float* b2 = (const float*)d_in[5];
    float* out = (float*)d_out;

    stage1_kernel<<<dim3(256, 4), 256>>>(yt, Ht);
    fused_conv_kernel<<<dim3(64, 32), 256>>>(W1, b1, W2, b2, out);
}